// round 1
// baseline (speedup 1.0000x reference)
#include <cuda_runtime.h>
#include <math.h>

// Problem constants
#define PB 4        // batch
#define PC 512      // channels
#define PCK 64      // key channels
#define PN 4096     // spatial (64*64)

// ---------------- scratch (static device memory; no allocs) ----------------
__device__ float g_WkT[PC * PCK];                 // [512][64]
__device__ float g_WvT[PC * PC];                  // [512][512]
__device__ float g_qk[PB * PCK * PN];             // [b][ck][n]
__device__ float g_vt[(size_t)PB * PN * PC];      // [b][m][c]  (value transposed)
__device__ float g_att[(size_t)PB * PN * PN];     // [b][m][n]  raw scores -> E[m][n]=att[n][m]
__device__ float g_outt[(size_t)PB * PN * PC];    // [b][n][c]
__device__ float g_mx[PB * PN];
__device__ float g_invl[PB * PN];

// ---------------- generic transpose (for weights) ----------------
__global__ void transpose_kernel(const float* __restrict__ in, float* __restrict__ out,
                                 int rows, int cols) {
    __shared__ float tile[32][33];
    int c0 = blockIdx.x * 32;
    int r0 = blockIdx.y * 32;
    int tx = threadIdx.x, ty = threadIdx.y; // 32 x 8
    for (int k = 0; k < 4; k++) {
        int r = r0 + ty + k * 8;
        int c = c0 + tx;
        if (r < rows && c < cols) tile[ty + k * 8][tx] = in[(size_t)r * cols + c];
    }
    __syncthreads();
    for (int k = 0; k < 4; k++) {
        int r = r0 + tx;              // row of input -> col of output
        int c = c0 + ty + k * 8;      // col of input -> row of output
        if (r < rows && c < cols) out[(size_t)c * rows + r] = tile[tx][ty + k * 8];
    }
}

// ---------------- generic K-major SGEMM: C[m,n] = sum_k A[k,m]*B[k,n] ------
// A: [K x M] row-major, B: [K x N] row-major, C: [M x N] row-major.
// biasMode: 0 none, 1 row bias (bias[m]), 2 col bias (bias[n]).
#define BM 128
#define BN 128
#define BK 8

__global__ void __launch_bounds__(256)
gemm_tn_kernel(const float* __restrict__ Aall, const float* __restrict__ Ball,
               float* __restrict__ Call,
               int M, int N, int K,
               long long sA, long long sB, long long sC,
               const float* __restrict__ bias, int biasMode) {
    const float* A = Aall + (long long)blockIdx.z * sA;
    const float* B = Ball + (long long)blockIdx.z * sB;
    float* Cm = Call + (long long)blockIdx.z * sC;

    __shared__ float As[BK][BM];
    __shared__ float Bs[BK][BN];

    int n0 = blockIdx.x * BN;
    int m0 = blockIdx.y * BM;
    int t = threadIdx.x;

    int lk = t >> 5;            // 0..7
    int lm = (t & 31) << 2;     // 0..124 step 4

    int ty = t >> 4;            // 0..15
    int tx = t & 15;            // 0..15

    float acc[8][8];
#pragma unroll
    for (int i = 0; i < 8; i++)
#pragma unroll
        for (int j = 0; j < 8; j++) acc[i][j] = 0.f;

    for (int k0 = 0; k0 < K; k0 += BK) {
        // load A tile
        {
            int gm = m0 + lm;
            float4 v;
            if (gm < M) v = *(const float4*)(A + (long long)(k0 + lk) * M + gm);
            else        v = make_float4(0.f, 0.f, 0.f, 0.f);
            *(float4*)&As[lk][lm] = v;
        }
        // load B tile
        {
            int gn = n0 + lm;
            float4 v;
            if (gn < N) v = *(const float4*)(B + (long long)(k0 + lk) * N + gn);
            else        v = make_float4(0.f, 0.f, 0.f, 0.f);
            *(float4*)&Bs[lk][lm] = v;
        }
        __syncthreads();
#pragma unroll
        for (int kk = 0; kk < BK; kk++) {
            float ra[8], rb[8];
            *(float4*)(ra)     = *(float4*)&As[kk][ty * 8];
            *(float4*)(ra + 4) = *(float4*)&As[kk][ty * 8 + 4];
            *(float4*)(rb)     = *(float4*)&Bs[kk][tx * 8];
            *(float4*)(rb + 4) = *(float4*)&Bs[kk][tx * 8 + 4];
#pragma unroll
            for (int i = 0; i < 8; i++)
#pragma unroll
                for (int j = 0; j < 8; j++) acc[i][j] += ra[i] * rb[j];
        }
        __syncthreads();
    }

    float bcol[8];
#pragma unroll
    for (int j = 0; j < 8; j++)
        bcol[j] = (biasMode == 2) ? bias[n0 + tx * 8 + j] : 0.f;

#pragma unroll
    for (int i = 0; i < 8; i++) {
        int gm = m0 + ty * 8 + i;
        if (gm < M) {
            float brow = (biasMode == 1) ? bias[gm] : 0.f;
            float4 v0, v1;
            v0.x = acc[i][0] + brow + bcol[0];
            v0.y = acc[i][1] + brow + bcol[1];
            v0.z = acc[i][2] + brow + bcol[2];
            v0.w = acc[i][3] + brow + bcol[3];
            v1.x = acc[i][4] + brow + bcol[4];
            v1.y = acc[i][5] + brow + bcol[5];
            v1.z = acc[i][6] + brow + bcol[6];
            v1.w = acc[i][7] + brow + bcol[7];
            float* cp = Cm + (long long)gm * N + n0 + tx * 8;
            *(float4*)(cp)     = v0;
            *(float4*)(cp + 4) = v1;
        }
    }
}

// ---------------- row max + inv(sum exp) per attention row -----------------
__device__ __forceinline__ float warpMax(float v) {
#pragma unroll
    for (int o = 16; o; o >>= 1) v = fmaxf(v, __shfl_xor_sync(0xFFFFFFFFu, v, o));
    return v;
}
__device__ __forceinline__ float warpSum(float v) {
#pragma unroll
    for (int o = 16; o; o >>= 1) v += __shfl_xor_sync(0xFFFFFFFFu, v, o);
    return v;
}

__global__ void __launch_bounds__(128)
rowstats_kernel(const float* __restrict__ S, float* __restrict__ mx,
                float* __restrict__ invl) {
    long long row = blockIdx.x;                 // b*N + n
    const float* r = S + row * PN;
    int t = threadIdx.x;
    float v[32];
    float m = -1e30f;
#pragma unroll
    for (int i = 0; i < 8; i++) {
        float4 f = *(const float4*)(r + i * 512 + t * 4);
        v[i * 4 + 0] = f.x; v[i * 4 + 1] = f.y; v[i * 4 + 2] = f.z; v[i * 4 + 3] = f.w;
        m = fmaxf(m, fmaxf(fmaxf(f.x, f.y), fmaxf(f.z, f.w)));
    }
    __shared__ float red[4];
    m = warpMax(m);
    if ((t & 31) == 0) red[t >> 5] = m;
    __syncthreads();
    m = fmaxf(fmaxf(red[0], red[1]), fmaxf(red[2], red[3]));

    float s = 0.f;
#pragma unroll
    for (int i = 0; i < 32; i++) s += __expf(v[i] - m);
    __syncthreads();
    s = warpSum(s);
    if ((t & 31) == 0) red[t >> 5] = s;
    __syncthreads();
    if (t == 0) {
        float tot = red[0] + red[1] + red[2] + red[3];
        mx[row] = m;
        invl[row] = 1.f / tot;
    }
}

// ---------------- in-place normalize using symmetry ------------------------
// E[m][n] := exp(s[m][n] - mx[col n]) * invl[col n]  ( == att[n][m] )
__global__ void __launch_bounds__(256)
normalize_kernel(float* __restrict__ S, const float* __restrict__ mx,
                 const float* __restrict__ invl) {
    long long idx4 = (long long)blockIdx.x * blockDim.x + threadIdx.x;
    long long e = idx4 * 4;                       // element index in [B*N*N)
    int n = (int)(e & (PN - 1));                  // column
    int b = (int)(e >> 24);                       // N*N = 2^24
    const float4 m4 = *(const float4*)(mx + (long long)b * PN + n);
    const float4 i4 = *(const float4*)(invl + (long long)b * PN + n);
    float4 s = *(float4*)(S + e);
    s.x = __expf(s.x - m4.x) * i4.x;
    s.y = __expf(s.y - m4.y) * i4.y;
    s.z = __expf(s.z - m4.z) * i4.z;
    s.w = __expf(s.w - m4.w) * i4.w;
    *(float4*)(S + e) = s;
}

// ---------------- epilogue: out[b,c,n] = gamma*outt[b,n,c] + x[b,c,n] ------
__global__ void __launch_bounds__(256)
epilogue_kernel(const float* __restrict__ OT, const float* __restrict__ x,
                const float* __restrict__ gamma, float* __restrict__ out) {
    __shared__ float tile[32][33];
    int b = blockIdx.z;
    int c0 = blockIdx.x * 32;
    int n0 = blockIdx.y * 32;
    int tx = threadIdx.x, ty = threadIdx.y; // 32 x 8
    const float* ot = OT + (size_t)b * PN * PC;
#pragma unroll
    for (int k = 0; k < 4; k++) {
        int n = n0 + ty + k * 8;
        tile[ty + k * 8][tx] = ot[(size_t)n * PC + c0 + tx];
    }
    __syncthreads();
    float g = __ldg(gamma);
#pragma unroll
    for (int k = 0; k < 4; k++) {
        int c = c0 + ty + k * 8;
        size_t o = ((size_t)b * PC + c) * PN + n0 + tx;
        out[o] = g * tile[tx][ty + k * 8] + x[o];
    }
}

// ---------------- launch ----------------------------------------------------
extern "C" void kernel_launch(void* const* d_in, const int* in_sizes, int n_in,
                              void* d_out, int out_size) {
    const float* x     = (const float*)d_in[0];
    const float* Wk    = (const float*)d_in[1];
    const float* bk    = (const float*)d_in[2];
    const float* Wv    = (const float*)d_in[3];
    const float* bv    = (const float*)d_in[4];
    const float* gamma = (const float*)d_in[5];
    float* out = (float*)d_out;

    float *p_WkT, *p_WvT, *p_qk, *p_vt, *p_att, *p_outt, *p_mx, *p_invl;
    cudaGetSymbolAddress((void**)&p_WkT,  g_WkT);
    cudaGetSymbolAddress((void**)&p_WvT,  g_WvT);
    cudaGetSymbolAddress((void**)&p_qk,   g_qk);
    cudaGetSymbolAddress((void**)&p_vt,   g_vt);
    cudaGetSymbolAddress((void**)&p_att,  g_att);
    cudaGetSymbolAddress((void**)&p_outt, g_outt);
    cudaGetSymbolAddress((void**)&p_mx,   g_mx);
    cudaGetSymbolAddress((void**)&p_invl, g_invl);

    dim3 t32x8(32, 8);

    // 1) weight transposes
    transpose_kernel<<<dim3(PC / 32, PCK / 32), t32x8>>>(Wk, p_WkT, PCK, PC);
    transpose_kernel<<<dim3(PC / 32, PC / 32), t32x8>>>(Wv, p_WvT, PC, PC);

    // 2) qk[b][o][n] = sum_c WkT[c][o] * x[b][c][n] + bk[o]   (M=64,N=4096,K=512)
    gemm_tn_kernel<<<dim3(PN / BN, 1, PB), 256>>>(
        p_WkT, x, p_qk, PCK, PN, PC,
        0LL, (long long)PC * PN, (long long)PCK * PN, bk, 1);

    // 3) vt[b][n][c] = sum_k x[b][k][n] * WvT[k][c] + bv[c]   (M=4096,N=512,K=512)
    gemm_tn_kernel<<<dim3(PC / BN, PN / BM, PB), 256>>>(
        x, p_WvT, p_vt, PN, PC, PC,
        (long long)PC * PN, 0LL, (long long)PN * PC, bv, 2);

    // 4) scores[b][n][m] = sum_ck qk[ck][n]*qk[ck][m]         (M=N=4096,K=64)
    gemm_tn_kernel<<<dim3(PN / BN, PN / BM, PB), 256>>>(
        p_qk, p_qk, p_att, PN, PN, PCK,
        (long long)PCK * PN, (long long)PCK * PN, (long long)PN * PN, (const float*)0, 0);

    // 5) softmax row stats
    rowstats_kernel<<<PB * PN, 128>>>(p_att, p_mx, p_invl);

    // 6) in-place normalize (uses symmetry: writes E[m][n] = att[n][m])
    {
        long long total4 = (long long)PB * PN * PN / 4;
        normalize_kernel<<<(unsigned)(total4 / 256), 256>>>(p_att, p_mx, p_invl);
    }

    // 7) outt[b][n][c] = sum_m E[m][n] * vt[m][c]             (M=4096,N=512,K=4096)
    gemm_tn_kernel<<<dim3(PC / BN, PN / BM, PB), 256>>>(
        p_att, p_vt, p_outt, PN, PC, PN,
        (long long)PN * PN, (long long)PN * PC, (long long)PN * PC, (const float*)0, 0);

    // 8) epilogue: transpose + gamma*out + x
    epilogue_kernel<<<dim3(PC / 32, PN / 32, PB), t32x8>>>(p_outt, x, gamma, out);
}

// round 3
// speedup vs baseline: 6.1814x; 6.1814x over previous
#include <cuda_runtime.h>
#include <cuda_bf16.h>
#include <cstdint>
#include <cstddef>

#define PB 4
#define PC 512
#define PCK 64
#define PN 4096

typedef __nv_bfloat16 bf16;

// ---------------- static scratch ----------------
__device__ bf16  g_xT[(size_t)PB * PN * PC];     // [b][n][c]
__device__ bf16  g_Wkb[PCK * PC];
__device__ bf16  g_Wvb[PC * PC];
__device__ bf16  g_qkt[(size_t)PB * PN * PCK];   // [b][n][ck]
__device__ bf16  g_v[(size_t)PB * PC * PN];      // [b][c][m]
__device__ float g_S[(size_t)PB * PN * PN];      // [b][n][m]
__device__ bf16  g_attb[(size_t)PB * PN * PN];   // [b][n][m]

// ---------------- helpers ----------------
static __device__ __forceinline__ uint32_t s2u(const void* p) {
    uint32_t a;
    asm("{ .reg .u64 t; cvta.to.shared.u64 t, %1; cvt.u32.u64 %0, t; }" : "=r"(a) : "l"(p));
    return a;
}
static __device__ __forceinline__ void cp16(uint32_t dst, const void* src) {
    asm volatile("cp.async.cg.shared.global [%0], [%1], 16;" :: "r"(dst), "l"(src));
}
static __device__ __forceinline__ void ldm4(uint32_t a, uint32_t* r) {
    asm volatile("ldmatrix.sync.aligned.m8n8.x4.shared.b16 {%0,%1,%2,%3}, [%4];"
                 : "=r"(r[0]), "=r"(r[1]), "=r"(r[2]), "=r"(r[3]) : "r"(a));
}
static __device__ __forceinline__ void mma16816(float* d, const uint32_t* a,
                                                uint32_t b0, uint32_t b1) {
    asm volatile(
        "mma.sync.aligned.m16n8k16.row.col.f32.bf16.bf16.f32 "
        "{%0,%1,%2,%3}, {%4,%5,%6,%7}, {%8,%9}, {%0,%1,%2,%3};"
        : "+f"(d[0]), "+f"(d[1]), "+f"(d[2]), "+f"(d[3])
        : "r"(a[0]), "r"(a[1]), "r"(a[2]), "r"(a[3]), "r"(b0), "r"(b1));
}

// load a tile of `rows` x 64 bf16 (128B/row) into swizzled smem
static __device__ __forceinline__ void load_tile(uint32_t sm, const bf16* g, int ld,
                                                 int rows, int tid) {
    for (int u = tid; u < rows * 8; u += 256) {
        int r = u >> 3, c = u & 7;
        cp16(sm + (uint32_t)(r * 128 + ((c ^ (r & 7)) << 4)), g + (size_t)r * ld + c * 8);
    }
}

// ---------------- generic bf16 warp-MMA GEMM ----------------
// D[m][n] = sum_k A[m][k]*B[n][k];  A,B K-major bf16.  M-tile 128, N-tile NTILE, BK=64.
// MODE 0: fp32 store. 1: +bias[n] -> bf16. 2: +bias[m] -> bf16. 3: gamma*D + x -> fp32.
template <int NTILE, int MODE>
__global__ void __launch_bounds__(256)
tc_gemm(const bf16* __restrict__ Aall, const bf16* __restrict__ Ball,
        void* __restrict__ Call, int K, int lda, int ldb, int ldc,
        long long sA, long long sB, long long sC,
        const float* __restrict__ bias, const float* __restrict__ xres,
        const float* __restrict__ gscale) {
    constexpr int ABYT = 128 * 128;            // A stage bytes
    constexpr int BBYT = NTILE * 128;
    constexpr int STG  = ABYT + BBYT;
    constexpr int NT_W = NTILE / 4;            // per-warp n extent
    constexpr int NFRag = NT_W / 8;            // n8 fragments per warp
    extern __shared__ __align__(1024) char smem[];

    const int tid = threadIdx.x;
    const int wid = tid >> 5;
    const int lane = tid & 31;
    const int wm = wid >> 2;                   // 0..1  (64 rows each)
    const int wn = wid & 3;                    // 0..3
    const int bz = blockIdx.z;
    const int m0 = blockIdx.y * 128;
    const int n0 = blockIdx.x * NTILE;
    const uint32_t sbase = s2u(smem);

    const bf16* Ab = Aall + (size_t)bz * sA + (size_t)m0 * lda;
    const bf16* Bb = Ball + (size_t)bz * sB + (size_t)n0 * ldb;
    const int nK = K >> 6;

    float acc[4][NFRag][4];
#pragma unroll
    for (int i = 0; i < 4; i++)
#pragma unroll
        for (int j = 0; j < NFRag; j++)
#pragma unroll
            for (int q = 0; q < 4; q++) acc[i][j][q] = 0.f;

    // per-thread ldmatrix addressing pieces
    const int l15 = lane & 15;
    const int swz = lane & 7;                  // row&7 for this thread's rows
    const int cbase = lane >> 4;               // chunk base (0/1)

    // prologue: stages 0,1
#pragma unroll
    for (int j = 0; j < 2; j++) {
        if (j < nK) {
            uint32_t s = sbase + j * STG;
            load_tile(s, Ab + j * 64, lda, 128, tid);
            load_tile(s + ABYT, Bb + j * 64, ldb, NTILE, tid);
        }
        asm volatile("cp.async.commit_group;");
    }

    for (int i = 0; i < nK; i++) {
        asm volatile("cp.async.wait_group 1;");
        __syncthreads();
        // prefetch stage i+2 (slot is free: its compute finished last iteration)
        const int j = i + 2;
        if (j < nK) {
            uint32_t s = sbase + (j % 3) * STG;
            load_tile(s, Ab + j * 64, lda, 128, tid);
            load_tile(s + ABYT, Bb + j * 64, ldb, NTILE, tid);
        }
        asm volatile("cp.async.commit_group;");

        const uint32_t sA_ = sbase + (i % 3) * STG;
        const uint32_t sB_ = sA_ + ABYT;
#pragma unroll
        for (int ks = 0; ks < 4; ks++) {
            const int chunk = ks * 2 + cbase;
            uint32_t a[4][4];
#pragma unroll
            for (int mf = 0; mf < 4; mf++) {
                int row = wm * 64 + mf * 16 + l15;
                ldm4(sA_ + (uint32_t)(row * 128 + ((chunk ^ swz) << 4)), a[mf]);
            }
            uint32_t b[2 * ((NFRag + 1) / 2)][2];
#pragma unroll
            for (int np = 0; np < NFRag / 2; np++) {
                uint32_t r[4];
                int row = wn * NT_W + np * 16 + l15;
                ldm4(sB_ + (uint32_t)(row * 128 + ((chunk ^ swz) << 4)), r);
                b[2 * np][0] = r[0]; b[2 * np][1] = r[2];
                b[2 * np + 1][0] = r[1]; b[2 * np + 1][1] = r[3];
            }
#pragma unroll
            for (int mf = 0; mf < 4; mf++)
#pragma unroll
                for (int nf = 0; nf < NFRag; nf++)
                    mma16816(acc[mf][nf], a[mf], b[nf][0], b[nf][1]);
        }
    }

    // ---------------- epilogue (registers only) ----------------
    const int g = lane >> 2, tg = lane & 3;
    float gv = 0.f;
    if (MODE == 3) gv = __ldg(gscale);
#pragma unroll
    for (int mf = 0; mf < 4; mf++) {
#pragma unroll
        for (int nf = 0; nf < NFRag; nf++) {
            const float* d = acc[mf][nf];
            const int col = n0 + wn * NT_W + nf * 8 + tg * 2;
            const size_t row0 = (size_t)m0 + wm * 64 + mf * 16 + g;
            const size_t row1 = row0 + 8;
            const size_t o0 = (size_t)bz * sC + row0 * ldc + col;
            const size_t o1 = (size_t)bz * sC + row1 * ldc + col;
            if (MODE == 0) {
                float* C = (float*)Call;
                *(float2*)(C + o0) = make_float2(d[0], d[1]);
                *(float2*)(C + o1) = make_float2(d[2], d[3]);
            } else if (MODE == 1) {
                const float b0 = __ldg(bias + col), b1 = __ldg(bias + col + 1);
                bf16* C = (bf16*)Call;
                *(__nv_bfloat162*)(C + o0) = __floats2bfloat162_rn(d[0] + b0, d[1] + b1);
                *(__nv_bfloat162*)(C + o1) = __floats2bfloat162_rn(d[2] + b0, d[3] + b1);
            } else if (MODE == 2) {
                bf16* C = (bf16*)Call;
                const float br0 = __ldg(bias + row0), br1 = __ldg(bias + row1);
                *(__nv_bfloat162*)(C + o0) = __floats2bfloat162_rn(d[0] + br0, d[1] + br0);
                *(__nv_bfloat162*)(C + o1) = __floats2bfloat162_rn(d[2] + br1, d[3] + br1);
            } else {
                float* C = (float*)Call;
                float2 x0 = *(const float2*)(xres + o0);
                float2 x1 = *(const float2*)(xres + o1);
                *(float2*)(C + o0) = make_float2(fmaf(gv, d[0], x0.x), fmaf(gv, d[1], x0.y));
                *(float2*)(C + o1) = make_float2(fmaf(gv, d[2], x1.x), fmaf(gv, d[3], x1.y));
            }
        }
    }
}

// ---------------- prep kernels ----------------
__global__ void __launch_bounds__(256) xT_kernel(const float* __restrict__ x,
                                                 bf16* __restrict__ xt) {
    __shared__ float tile[32][33];
    const int b = blockIdx.z;
    const int n0 = blockIdx.x * 32, c0 = blockIdx.y * 32;
    const int tx = threadIdx.x, ty = threadIdx.y;
    const float* xb = x + (size_t)b * PC * PN;
#pragma unroll
    for (int k = 0; k < 4; k++) {
        int c = c0 + ty + k * 8;
        tile[ty + k * 8][tx] = xb[(size_t)c * PN + n0 + tx];
    }
    __syncthreads();
    bf16* ob = xt + (size_t)b * PN * PC;
#pragma unroll
    for (int k = 0; k < 4; k++) {
        int n = n0 + ty + k * 8;
        ob[(size_t)n * PC + c0 + tx] = __float2bfloat16(tile[tx][ty + k * 8]);
    }
}

__global__ void cvt_kernel(const float* __restrict__ in, bf16* __restrict__ out, int n) {
    int i = blockIdx.x * 256 + threadIdx.x;
    if (i < n) out[i] = __float2bfloat16(in[i]);
}

// ---------------- fused softmax ----------------
static __device__ __forceinline__ float warpMax(float v) {
#pragma unroll
    for (int o = 16; o; o >>= 1) v = fmaxf(v, __shfl_xor_sync(0xFFFFFFFFu, v, o));
    return v;
}
static __device__ __forceinline__ float warpSum(float v) {
#pragma unroll
    for (int o = 16; o; o >>= 1) v += __shfl_xor_sync(0xFFFFFFFFu, v, o);
    return v;
}

__global__ void __launch_bounds__(256)
softmax_kernel(const float* __restrict__ S, bf16* __restrict__ E) {
    const size_t row = blockIdx.x;
    const float* r = S + row * PN;
    const int t = threadIdx.x;
    float v[16];
    float m = -1e30f;
#pragma unroll
    for (int i = 0; i < 4; i++) {
        float4 f = *(const float4*)(r + i * 1024 + t * 4);
        v[i * 4 + 0] = f.x; v[i * 4 + 1] = f.y; v[i * 4 + 2] = f.z; v[i * 4 + 3] = f.w;
        m = fmaxf(m, fmaxf(fmaxf(f.x, f.y), fmaxf(f.z, f.w)));
    }
    __shared__ float redm[8], reds[8];
    m = warpMax(m);
    if ((t & 31) == 0) redm[t >> 5] = m;
    __syncthreads();
    m = redm[0];
#pragma unroll
    for (int i = 1; i < 8; i++) m = fmaxf(m, redm[i]);

    float s = 0.f;
#pragma unroll
    for (int i = 0; i < 16; i++) s += __expf(v[i] - m);
    s = warpSum(s);
    if ((t & 31) == 0) reds[t >> 5] = s;
    __syncthreads();
    float tot = reds[0];
#pragma unroll
    for (int i = 1; i < 8; i++) tot += reds[i];
    const float il = 1.f / tot;

    bf16* o = E + row * PN;
#pragma unroll
    for (int i = 0; i < 4; i++) {
        float e0 = __expf(v[i * 4 + 0] - m) * il;
        float e1 = __expf(v[i * 4 + 1] - m) * il;
        float e2 = __expf(v[i * 4 + 2] - m) * il;
        float e3 = __expf(v[i * 4 + 3] - m) * il;
        bf16* p = o + i * 1024 + t * 4;
        *(__nv_bfloat162*)(p) = __floats2bfloat162_rn(e0, e1);
        *(__nv_bfloat162*)(p + 2) = __floats2bfloat162_rn(e2, e3);
    }
}

// ---------------- launch ----------------
extern "C" void kernel_launch(void* const* d_in, const int* in_sizes, int n_in,
                              void* d_out, int out_size) {
    const float* x     = (const float*)d_in[0];
    const float* Wk    = (const float*)d_in[1];
    const float* bk    = (const float*)d_in[2];
    const float* Wv    = (const float*)d_in[3];
    const float* bv    = (const float*)d_in[4];
    const float* gamma = (const float*)d_in[5];
    float* out = (float*)d_out;

    bf16 *p_xT, *p_Wkb, *p_Wvb, *p_qkt, *p_v, *p_attb;
    float *p_S;
    cudaGetSymbolAddress((void**)&p_xT,   g_xT);
    cudaGetSymbolAddress((void**)&p_Wkb,  g_Wkb);
    cudaGetSymbolAddress((void**)&p_Wvb,  g_Wvb);
    cudaGetSymbolAddress((void**)&p_qkt,  g_qkt);
    cudaGetSymbolAddress((void**)&p_v,    g_v);
    cudaGetSymbolAddress((void**)&p_S,    g_S);
    cudaGetSymbolAddress((void**)&p_attb, g_attb);

    const int SM64  = 3 * (128 + 64) * 128;    // 73728
    const int SM128 = 3 * (128 + 128) * 128;   // 98304
    cudaFuncSetAttribute(tc_gemm<64, 1>,  cudaFuncAttributeMaxDynamicSharedMemorySize, SM64);
    cudaFuncSetAttribute(tc_gemm<128, 0>, cudaFuncAttributeMaxDynamicSharedMemorySize, SM128);
    cudaFuncSetAttribute(tc_gemm<128, 2>, cudaFuncAttributeMaxDynamicSharedMemorySize, SM128);
    cudaFuncSetAttribute(tc_gemm<128, 3>, cudaFuncAttributeMaxDynamicSharedMemorySize, SM128);

    // prep
    cvt_kernel<<<(PCK * PC + 255) / 256, 256>>>(Wk, p_Wkb, PCK * PC);
    cvt_kernel<<<(PC * PC + 255) / 256, 256>>>(Wv, p_Wvb, PC * PC);
    xT_kernel<<<dim3(PN / 32, PC / 32, PB), dim3(32, 8)>>>(x, p_xT);

    // qkt[b][n][o] = xT[n][:]·Wk[o][:] + bk[o]      (M=4096, N=64, K=512)
    tc_gemm<64, 1><<<dim3(1, PN / 128, PB), 256, SM64>>>(
        p_xT, p_Wkb, p_qkt, PC, PC, PC, PCK,
        (long long)PN * PC, 0LL, (long long)PN * PCK, bk, nullptr, nullptr);

    // v[b][c][n] = Wv[c][:]·xT[n][:] + bv[c]        (M=512, N=4096, K=512)
    tc_gemm<128, 2><<<dim3(PN / 128, PC / 128, PB), 256, SM128>>>(
        p_Wvb, p_xT, p_v, PC, PC, PC, PN,
        0LL, (long long)PN * PC, (long long)PC * PN, bv, nullptr, nullptr);

    // S[b][n][m] = qkt[n][:]·qkt[m][:]              (M=4096, N=4096, K=64)
    tc_gemm<128, 0><<<dim3(PN / 128, PN / 128, PB), 256, SM128>>>(
        p_qkt, p_qkt, p_S, PCK, PCK, PCK, PN,
        (long long)PN * PCK, (long long)PN * PCK, (long long)PN * PN,
        nullptr, nullptr, nullptr);

    softmax_kernel<<<PB * PN, 256>>>(p_S, p_attb);

    // out[b][c][n] = gamma * (v[c][:]·att[n][:]) + x[b][c][n]   (M=512, N=4096, K=4096)
    tc_gemm<128, 3><<<dim3(PN / 128, PC / 128, PB), 256, SM128>>>(
        p_v, p_attb, out, PN, PN, PN, PN,
        (long long)PC * PN, (long long)PN * PN, (long long)PC * PN,
        nullptr, x, gamma);
}